// round 1
// baseline (speedup 1.0000x reference)
#include <cuda_runtime.h>
#include <cuda_bf16.h>

// out = conv3x3( f(img), W ) / 27 with zero padding on the transformed input.
// f(x) = P01 + P11*x + P21*x^2. Identity-kernel branch of the reference is
// exactly zero (all its poly coefficients are 0.0), so it is omitted.

#define TILE    16
#define CCH     8          // input channels per smem chunk
#define XROWS   18         // TILE + 2 halo
#define XSTRIDE 19         // odd stride -> conflict-free lane pattern
#define C_IN    64
#define C_OUT   64
#define HW      128

__global__ __launch_bounds__(256, 2)
void conv_poly_kernel(const float* __restrict__ img,
                      const float* __restrict__ wgt,
                      float* __restrict__ out)
{
    __shared__ float sX[CCH * XROWS * XSTRIDE];   // 10.9 KB
    __shared__ float sW[C_OUT * CCH * 9];         // 18.4 KB  layout [k][c*9+r*3+s]

    const int tid    = threadIdx.x;
    const int warp   = tid >> 5;
    const int lane   = tid & 31;
    const int kbase  = warp * 8;            // 8 output channels per warp
    const int row    = lane >> 1;           // 0..15
    const int colseg = (lane & 1) * 8;      // 0 or 8

    const int x0 = blockIdx.x * TILE;
    const int y0 = blockIdx.y * TILE;
    const int n  = blockIdx.z;

    const float P01 = -0.000287f, P11 = 0.266f, P21 = -0.1097f;

    float acc[8][8];
    #pragma unroll
    for (int i = 0; i < 8; i++)
        #pragma unroll
        for (int j = 0; j < 8; j++) acc[i][j] = 0.f;

    for (int c0 = 0; c0 < C_IN; c0 += CCH) {
        // ---- fill input tile (poly fused, zero halo) ----
        for (int idx = tid; idx < CCH * XROWS * XROWS; idx += 256) {
            int c   = idx / (XROWS * XROWS);
            int rem = idx - c * (XROWS * XROWS);
            int ry  = rem / XROWS;
            int rx  = rem - ry * XROWS;
            int gy  = y0 + ry - 1;
            int gx  = x0 + rx - 1;
            float v = 0.f;
            if ((unsigned)gy < HW && (unsigned)gx < HW) {
                float x = img[((size_t)(n * C_IN + c0 + c) * HW + gy) * HW + gx];
                v = fmaf(fmaf(P21, x, P11), x, P01);
            }
            sX[c * (XROWS * XSTRIDE) + ry * XSTRIDE + rx] = v;
        }
        // ---- fill weight tile: sW[k][j], j = c_local*9 + r*3 + s ----
        // global weights are [k][c][3][3] with (c,r,s) contiguous per k,
        // so reads here are coalesced runs of 72 floats.
        for (int idx = tid; idx < C_OUT * CCH * 9; idx += 256) {
            int k = idx / 72;
            int j = idx - k * 72;
            sW[k * 72 + j] = wgt[k * 576 + c0 * 9 + j];
        }
        __syncthreads();

        // ---- compute ----
        #pragma unroll
        for (int c = 0; c < CCH; c++) {
            #pragma unroll
            for (int r = 0; r < 3; r++) {
                float xr[10];
                const float* xp = &sX[c * (XROWS * XSTRIDE) + (row + r) * XSTRIDE + colseg];
                #pragma unroll
                for (int i = 0; i < 10; i++) xr[i] = xp[i];
                #pragma unroll
                for (int s = 0; s < 3; s++) {
                    float wv[8];
                    #pragma unroll
                    for (int k8 = 0; k8 < 8; k8++)
                        wv[k8] = sW[(kbase + k8) * 72 + c * 9 + r * 3 + s]; // broadcast
                    #pragma unroll
                    for (int k8 = 0; k8 < 8; k8++)
                        #pragma unroll
                        for (int p = 0; p < 8; p++)
                            acc[k8][p] = fmaf(wv[k8], xr[s + p], acc[k8][p]);
                }
            }
        }
        __syncthreads();
    }

    // ---- epilogue: scale by 1/27, vectorized stores ----
    const float scale = 1.f / 27.f;
    #pragma unroll
    for (int k8 = 0; k8 < 8; k8++) {
        float* po = &out[(((size_t)(n * C_OUT + kbase + k8)) * HW + (y0 + row)) * HW + x0 + colseg];
        float4 v0, v1;
        v0.x = acc[k8][0] * scale; v0.y = acc[k8][1] * scale;
        v0.z = acc[k8][2] * scale; v0.w = acc[k8][3] * scale;
        v1.x = acc[k8][4] * scale; v1.y = acc[k8][5] * scale;
        v1.z = acc[k8][6] * scale; v1.w = acc[k8][7] * scale;
        reinterpret_cast<float4*>(po)[0] = v0;
        reinterpret_cast<float4*>(po)[1] = v1;
    }
}

extern "C" void kernel_launch(void* const* d_in, const int* in_sizes, int n_in,
                              void* d_out, int out_size)
{
    const float* img = (const float*)d_in[0];
    const float* wgt = (const float*)d_in[1];
    // d_in[2] (identity_kernel) is mathematically irrelevant: its input branch
    // is identically zero in the reference.
    float* out = (float*)d_out;

    int N = in_sizes[0] / (C_IN * HW * HW);   // 16
    dim3 grid(HW / TILE, HW / TILE, N);
    conv_poly_kernel<<<grid, 256>>>(img, wgt, out);
}

// round 2
// speedup vs baseline: 1.0420x; 1.0420x over previous
#include <cuda_runtime.h>
#include <cuda_bf16.h>

// out = conv3x3( f(img), W ) / 27, f(x) = P01 + P11*x + P21*x^2, zero pad.
// Identity-kernel branch of the reference is exactly zero and omitted.
// Round 2: packed fp32 FMA (fma.rn.f32x2) -> 2x FMA throughput per SM.

#define TILE    16
#define CCH     4          // input channels per smem chunk
#define XROWS   18         // TILE + 2 halo; also the row stride (even, 8B-aligned pairs)
#define C_IN    64
#define C_OUT   64
#define HW      128

typedef unsigned long long u64;

__device__ __forceinline__ u64 pack2(float lo, float hi) {
    u64 r; asm("mov.b64 %0, {%1,%2};" : "=l"(r) : "f"(lo), "f"(hi)); return r;
}
__device__ __forceinline__ void unpack2(u64 v, float& lo, float& hi) {
    asm("mov.b64 {%0,%1}, %2;" : "=f"(lo), "=f"(hi) : "l"(v));
}
__device__ __forceinline__ void ffma2(u64& d, u64 a, u64 b) {
    asm("fma.rn.f32x2 %0, %1, %2, %0;" : "+l"(d) : "l"(a), "l"(b));
}
__device__ __forceinline__ u64 mul2(u64 a, u64 b) {
    u64 r; asm("mul.rn.f32x2 %0, %1, %2;" : "=l"(r) : "l"(a), "l"(b)); return r;
}

__global__ __launch_bounds__(256, 2)
void conv_poly_f32x2_kernel(const float* __restrict__ img,
                            const float* __restrict__ wgt,
                            float* __restrict__ out)
{
    __shared__ float sX[CCH * XROWS * XROWS];     // 5.1 KB
    __shared__ u64   sW2[C_OUT * CCH * 9];        // 18.4 KB, (w,w) duplicated

    const int tid    = threadIdx.x;
    const int warp   = tid >> 5;
    const int lane   = tid & 31;
    const int kbase  = warp * 8;            // 8 output channels per warp
    const int row    = lane & 15;           // 0..15  (half-warp = 16 rows -> bank-free LDS.64)
    const int colseg = (lane >> 4) * 8;     // 0 or 8

    const int x0 = blockIdx.x * TILE;
    const int y0 = blockIdx.y * TILE;
    const int n  = blockIdx.z;

    const float P01 = -0.000287f, P11 = 0.266f, P21 = -0.1097f;

    u64 acc[8][4];                          // 8 k-channels x 4 pixel-pairs
    #pragma unroll
    for (int k8 = 0; k8 < 8; k8++)
        #pragma unroll
        for (int j = 0; j < 4; j++) acc[k8][j] = 0ull;

    for (int c0 = 0; c0 < C_IN; c0 += CCH) {
        // ---- fill input tile (poly fused, zero halo) ----
        #pragma unroll
        for (int it = 0; it < (CCH * XROWS * XROWS + 255) / 256; it++) {
            int idx = tid + it * 256;
            if (idx < CCH * XROWS * XROWS) {
                int c   = idx / (XROWS * XROWS);
                int rem = idx - c * (XROWS * XROWS);
                int ry  = rem / XROWS;
                int rx  = rem - ry * XROWS;
                int gy  = y0 + ry - 1;
                int gx  = x0 + rx - 1;
                float v = 0.f;
                if ((unsigned)gy < HW && (unsigned)gx < HW) {
                    float x = img[((size_t)(n * C_IN + c0 + c) * HW + gy) * HW + gx];
                    v = fmaf(fmaf(P21, x, P11), x, P01);
                }
                sX[idx] = v;
            }
        }
        // ---- fill duplicated weights: sW2[k][c*9+r*3+s] = (w,w) ----
        #pragma unroll
        for (int it = 0; it < (C_OUT * CCH * 9 + 255) / 256; it++) {
            int idx = tid + it * 256;
            if (idx < C_OUT * CCH * 9) {
                int k = idx / (CCH * 9);
                int j = idx - k * (CCH * 9);
                float w = wgt[k * 576 + c0 * 9 + j];
                sW2[idx] = pack2(w, w);
            }
        }
        __syncthreads();

        // ---- compute ----
        #pragma unroll
        for (int c = 0; c < CCH; c++) {
            #pragma unroll
            for (int r = 0; r < 3; r++) {
                const u64* xp = reinterpret_cast<const u64*>(
                    &sX[(c * XROWS + (row + r)) * XROWS + colseg]);
                u64 P[5];
                #pragma unroll
                for (int j = 0; j < 5; j++) P[j] = xp[j];
                float xl[5], xh[5];
                #pragma unroll
                for (int j = 0; j < 5; j++) unpack2(P[j], xl[j], xh[j]);
                u64 Q[4];
                #pragma unroll
                for (int j = 0; j < 4; j++) Q[j] = pack2(xh[j], xl[j + 1]);

                const u64* wp = &sW2[kbase * (CCH * 9) + c * 9 + r * 3];
                #pragma unroll
                for (int s = 0; s < 3; s++) {
                    u64 W[8];
                    #pragma unroll
                    for (int k8 = 0; k8 < 8; k8++)
                        W[k8] = wp[k8 * (CCH * 9) + s];     // broadcast LDS.64
                    #pragma unroll
                    for (int k8 = 0; k8 < 8; k8++) {
                        #pragma unroll
                        for (int j = 0; j < 4; j++) {
                            u64 b = (s == 0) ? P[j] : (s == 1) ? Q[j] : P[j + 1];
                            ffma2(acc[k8][j], W[k8], b);
                        }
                    }
                }
            }
        }
        __syncthreads();
    }

    // ---- epilogue: scale by 1/27, 16B stores ----
    const u64 scale2 = pack2(1.f / 27.f, 1.f / 27.f);
    #pragma unroll
    for (int k8 = 0; k8 < 8; k8++) {
        u64* po = reinterpret_cast<u64*>(
            &out[(((size_t)(n * C_OUT + kbase + k8)) * HW + (y0 + row)) * HW + x0 + colseg]);
        ulonglong2 v0, v1;
        v0.x = mul2(acc[k8][0], scale2);
        v0.y = mul2(acc[k8][1], scale2);
        v1.x = mul2(acc[k8][2], scale2);
        v1.y = mul2(acc[k8][3], scale2);
        reinterpret_cast<ulonglong2*>(po)[0] = v0;
        reinterpret_cast<ulonglong2*>(po)[1] = v1;
    }
}

extern "C" void kernel_launch(void* const* d_in, const int* in_sizes, int n_in,
                              void* d_out, int out_size)
{
    const float* img = (const float*)d_in[0];
    const float* wgt = (const float*)d_in[1];
    float* out = (float*)d_out;

    int N = in_sizes[0] / (C_IN * HW * HW);   // 16
    dim3 grid(HW / TILE, HW / TILE, N);
    conv_poly_f32x2_kernel<<<grid, 256>>>(img, wgt, out);
}

// round 5
// speedup vs baseline: 2.4696x; 2.3701x over previous
#include <cuda_runtime.h>
#include <cuda_bf16.h>
#include <cstdint>

// out = conv3x3(f(img), W)/27, f(x)=P01+P11*x+P21*x^2, zero pad.
// Identity branch of the reference is exactly zero and omitted.
// Tensor path: ldmatrix + mma.sync.m16n8k16 bf16 (arch-portable PTX; tcgen05
// PTX is rejected by this build's compute_103 target). fp32 accuracy via
// 3-term bf16 split: x*w ~= xh*wh + xl*wh + xh*wl (error ~2^-16).

#define HW     128
#define CIN    64
#define COUT   64
#define BTILE  8192                 // one [64 n][64 k] bf16 tile, swizzled
#define ATILE  16640                // [130 px][64 c] bf16 tile (128 B rows)
#define AOFF   (18 * BTILE)         // 147456
#define DSMEM  (AOFF + 4 * ATILE)   // 214016 (2 bufs x 2 parts)

__device__ __nv_bfloat16 g_wsplit[18 * 4096];   // [tap*2+part][n=kout][k=cin]

__device__ __forceinline__ uint32_t smem_u32(const void* p) {
    uint32_t a;
    asm("{ .reg .u64 t; cvta.to.shared.u64 t, %1; cvt.u32.u64 %0, t; }" : "=r"(a) : "l"(p));
    return a;
}
__device__ __forceinline__ void ldsm4(uint32_t* r, uint32_t a) {
    asm volatile("ldmatrix.sync.aligned.m8n8.x4.shared.b16 {%0,%1,%2,%3}, [%4];"
        : "=r"(r[0]), "=r"(r[1]), "=r"(r[2]), "=r"(r[3]) : "r"(a));
}
__device__ __forceinline__ void mma_bf16(float* d, const uint32_t* a, const uint32_t* b) {
    asm volatile("mma.sync.aligned.m16n8k16.row.col.f32.bf16.bf16.f32 "
        "{%0,%1,%2,%3}, {%4,%5,%6,%7}, {%8,%9}, {%0,%1,%2,%3};"
        : "+f"(d[0]), "+f"(d[1]), "+f"(d[2]), "+f"(d[3])
        : "r"(a[0]), "r"(a[1]), "r"(a[2]), "r"(a[3]), "r"(b[0]), "r"(b[1]));
}

__global__ void wprep_kernel(const float* __restrict__ wgt) {
    int idx = blockIdx.x * 256 + threadIdx.x;
    if (idx >= 9 * 64 * 64) return;
    int t = idx >> 12, k = (idx >> 6) & 63, c = idx & 63;       // t=tap, k=kout, c=cin
    float w = wgt[(k * 64 + c) * 9 + t];                        // OIHW, tap = r*3+s
    __nv_bfloat16 wh = __float2bfloat16(w);
    __nv_bfloat16 wl = __float2bfloat16(w - __bfloat162float(wh));
    g_wsplit[(t * 2 + 0) * 4096 + k * 64 + c] = wh;
    g_wsplit[(t * 2 + 1) * 4096 + k * 64 + c] = wl;
}

__global__ __launch_bounds__(256, 1)
void conv_hmma_kernel(const float* __restrict__ img, float* __restrict__ out)
{
    extern __shared__ __align__(1024) char dsm[];
    const uint32_t sb = smem_u32(dsm);

    const int tid  = threadIdx.x, wid = tid >> 5, lane = tid & 31;
    const int n    = blockIdx.x >> 6;          // image
    const int yb   = (blockIdx.x & 63) * 2;    // output row pair (yb, yb+1)
    const int p0   = wid * 16;                 // warp's 16-px column
    const int px   = tid & 127, chalf = tid >> 7;

    // ---- fill swizzled W tiles (u32 = 2 k-adjacent bf16) ----
    const uint32_t* gw = reinterpret_cast<const uint32_t*>(g_wsplit);
    for (int j = tid; j < 18 * 2048; j += 256) {
        int t = j >> 11, rem = j & 2047;
        int nr = rem >> 5, kp = rem & 31;                       // k = 2*kp
        int off = t * BTILE + nr * 128 + (((kp >> 2) ^ (nr & 7)) << 4) + (kp & 3) * 4;
        *reinterpret_cast<uint32_t*>(dsm + off) = gw[j];
    }
    // ---- zero halo rows (0 and 129) of all 4 A subtiles ----
    {
        int t = tid >> 6, rem = tid & 63;
        int row = (rem >> 5) ? 129 : 0;
        *reinterpret_cast<uint32_t*>(dsm + AOFF + t * ATILE + row * 128 + (rem & 31) * 4) = 0u;
    }

    const float P01 = -0.000287f, P11 = 0.266f, P21 = -0.1097f;
    const int zlo = max(yb - 1, 0), zhi = min(yb + 2, HW - 1);

    float st[32];
    const float* ibase = img + ((size_t)(n * CIN + chalf * 32) * HW) * HW + px;

    // stage row z into registers
    auto STAGE = [&](int z) {
        const float* ip = ibase + (size_t)z * HW;
        #pragma unroll
        for (int i = 0; i < 32; i++) st[i] = ip[(size_t)i * HW * HW];
    };
    // poly + split + swizzled store to buffer
    auto STORE = [&](int buf) {
        char* a0 = dsm + AOFF + buf * 2 * ATILE;
        const int rs = px + 1;
        #pragma unroll
        for (int i = 0; i < 16; i++) {
            int c2 = chalf * 32 + 2 * i;
            float v0 = fmaf(fmaf(P21, st[2*i],   P11), st[2*i],   P01);
            float v1 = fmaf(fmaf(P21, st[2*i+1], P11), st[2*i+1], P01);
            __nv_bfloat16 h0 = __float2bfloat16(v0), h1 = __float2bfloat16(v1);
            __nv_bfloat16 l0 = __float2bfloat16(v0 - __bfloat162float(h0));
            __nv_bfloat16 l1 = __float2bfloat16(v1 - __bfloat162float(h1));
            uint32_t hp = ((uint32_t)__bfloat16_as_ushort(h1) << 16) | __bfloat16_as_ushort(h0);
            uint32_t lp = ((uint32_t)__bfloat16_as_ushort(l1) << 16) | __bfloat16_as_ushort(l0);
            int off = rs * 128 + ((((c2 >> 3) ^ (rs & 7))) << 4) + (c2 & 7) * 2;
            *reinterpret_cast<uint32_t*>(a0 + off)         = hp;
            *reinterpret_cast<uint32_t*>(a0 + ATILE + off) = lp;
        }
    };

    float acc[2][8][4];
    #pragma unroll
    for (int yi = 0; yi < 2; yi++)
        #pragma unroll
        for (int nt = 0; nt < 8; nt++)
            #pragma unroll
            for (int e = 0; e < 4; e++) acc[yi][nt][e] = 0.f;

    STAGE(zlo);
    STORE(0);
    __syncthreads();

    int buf = 0;
    for (int z = zlo; z <= zhi; z++) {
        if (z < zhi) STAGE(z + 1);     // issue LDGs early; latency hidden by MMAs

        #pragma unroll
        for (int s = 0; s < 3; s++) {
            // hoist A fragments for this shift: [part][kc][4]
            uint32_t af[2][4][4];
            const int rowA = p0 + s + (lane & 7) + ((lane >> 3) & 1) * 8;
            const int chA  = lane >> 4;
            #pragma unroll
            for (int part = 0; part < 2; part++) {
                uint32_t ab = sb + AOFF + (buf * 2 + part) * ATILE + rowA * 128;
                #pragma unroll
                for (int kc = 0; kc < 4; kc++) {
                    int ch = 2 * kc + chA;
                    ldsm4(af[part][kc], ab + ((ch ^ (rowA & 7)) << 4));
                }
            }
            #pragma unroll
            for (int yi = 0; yi < 2; yi++) {
                const int r = z - (yb + yi) + 1;
                if (r < 0 || r > 2) continue;          // tap rows outside 3x3
                #pragma unroll
                for (int term = 0; term < 3; term++) {  // hh, lh, hl
                    const uint32_t tb = sb + ((r * 3 + s) * 2 + (term == 2 ? 1 : 0)) * BTILE;
                    const int ap = (term == 1) ? 1 : 0;
                    #pragma unroll
                    for (int kc = 0; kc < 4; kc++) {
                        #pragma unroll
                        for (int nt2 = 0; nt2 < 4; nt2++) {
                            int nrow = (nt2 * 2 + (lane >> 4)) * 8 + (lane & 7);
                            int ch   = 2 * kc + ((lane >> 3) & 1);
                            uint32_t b[4];
                            ldsm4(b, tb + nrow * 128 + ((ch ^ (nrow & 7)) << 4));
                            mma_bf16(acc[yi][nt2 * 2],     af[ap][kc], b);
                            mma_bf16(acc[yi][nt2 * 2 + 1], af[ap][kc], b + 2);
                        }
                    }
                }
            }
        }

        if (z < zhi) STORE(buf ^ 1);
        buf ^= 1;
        __syncthreads();
    }

    // ---- epilogue: scale by 1/27, direct stores ----
    const float sc = 1.f / 27.f;
    #pragma unroll
    for (int yi = 0; yi < 2; yi++) {
        const int y = yb + yi;
        #pragma unroll
        for (int nt = 0; nt < 8; nt++) {
            int kout = nt * 8 + 2 * (lane & 3);
            int pxo  = p0 + (lane >> 2);
            float* o = out + ((size_t)(n * COUT + kout) * HW + y) * HW;
            o[pxo]               = acc[yi][nt][0] * sc;
            o[HW * HW + pxo]     = acc[yi][nt][1] * sc;   // kout+1
            o[pxo + 8]           = acc[yi][nt][2] * sc;
            o[HW * HW + pxo + 8] = acc[yi][nt][3] * sc;
        }
    }
}

extern "C" void kernel_launch(void* const* d_in, const int* in_sizes, int n_in,
                              void* d_out, int out_size)
{
    const float* img = (const float*)d_in[0];
    const float* wgt = (const float*)d_in[1];
    float* out = (float*)d_out;

    cudaFuncSetAttribute(conv_hmma_kernel,
                         cudaFuncAttributeMaxDynamicSharedMemorySize, DSMEM);

    int N = in_sizes[0] / (CIN * HW * HW);   // 16
    wprep_kernel<<<144, 256>>>(wgt);
    conv_hmma_kernel<<<N * 64, 256, DSMEM>>>(img, out);
}

// round 8
// speedup vs baseline: 2.5424x; 1.0295x over previous
#include <cuda_runtime.h>
#include <cuda_bf16.h>
#include <cstdint>

// out = conv3x3(f(img), W)/27, f(x)=P01+P11*x+P21*x^2, zero pad.
// ldmatrix + mma.sync.m16n8k16 bf16; fp32 accuracy via 3-term bf16 split.
// Round 6: tap-row-outer loop, A 3-slot ring + B 2-group ring, B fragments
// loaded once per tap (LDSM/warp 960 -> 432), uniform zero-padded edges.

#define HW     128
#define CIN    64
#define COUT   64
#define BTILE  8192                 // [64 n][64 k] bf16, swizzled
#define ATILE  16640                // [130 px][64 c] bf16 (128 B rows)
#define BGRP   (6 * BTILE)          // one tap-row group: 3 s x 2 parts
#define BOFF   0
#define AOFF   (2 * BGRP)           // 98304
#define DSMEM  (AOFF + 6 * ATILE)   // 198144

__device__ __nv_bfloat16 g_wsplit[18 * 4096];   // [tap*2+part][n=kout][k=cin]

__device__ __forceinline__ uint32_t smem_u32(const void* p) {
    uint32_t a;
    asm("{ .reg .u64 t; cvta.to.shared.u64 t, %1; cvt.u32.u64 %0, t; }" : "=r"(a) : "l"(p));
    return a;
}
__device__ __forceinline__ void ldsm4(uint32_t* r, uint32_t a) {
    asm volatile("ldmatrix.sync.aligned.m8n8.x4.shared.b16 {%0,%1,%2,%3}, [%4];"
        : "=r"(r[0]), "=r"(r[1]), "=r"(r[2]), "=r"(r[3]) : "r"(a));
}
__device__ __forceinline__ void mma_bf16(float* d, const uint32_t* a, const uint32_t* b) {
    asm volatile("mma.sync.aligned.m16n8k16.row.col.f32.bf16.bf16.f32 "
        "{%0,%1,%2,%3}, {%4,%5,%6,%7}, {%8,%9}, {%0,%1,%2,%3};"
        : "+f"(d[0]), "+f"(d[1]), "+f"(d[2]), "+f"(d[3])
        : "r"(a[0]), "r"(a[1]), "r"(a[2]), "r"(a[3]), "r"(b[0]), "r"(b[1]));
}

__global__ void wprep_kernel(const float* __restrict__ wgt) {
    int idx = blockIdx.x * 256 + threadIdx.x;
    if (idx >= 9 * 64 * 64) return;
    int t = idx >> 12, k = (idx >> 6) & 63, c = idx & 63;
    float w = wgt[(k * 64 + c) * 9 + t];
    __nv_bfloat16 wh = __float2bfloat16(w);
    __nv_bfloat16 wl = __float2bfloat16(w - __bfloat162float(wh));
    g_wsplit[(t * 2 + 0) * 4096 + k * 64 + c] = wh;
    g_wsplit[(t * 2 + 1) * 4096 + k * 64 + c] = wl;
}

__global__ __launch_bounds__(256, 1)
void conv_hmma_kernel(const float* __restrict__ img, float* __restrict__ out)
{
    extern __shared__ __align__(1024) char dsm[];
    const uint32_t sb = smem_u32(dsm);

    const int tid  = threadIdx.x, wid = tid >> 5, lane = tid & 31;
    const int n    = blockIdx.x >> 6;
    const int yb   = (blockIdx.x & 63) * 2;
    const int p0   = wid * 16;
    const int px   = tid & 127, chalf = tid >> 7;

    const float P01 = -0.000287f, P11 = 0.266f, P21 = -0.1097f;

    // fill A slot with input row z (poly + split + swizzle); zeros if out of range
    auto fillA = [&](int z, int slot) {
        char* a0 = dsm + AOFF + slot * 2 * ATILE;
        if ((unsigned)z < HW) {
            const float* ip = img + ((size_t)(n * CIN + chalf * 32) * HW + z) * HW + px;
            const int rs = px + 1;
            #pragma unroll
            for (int i = 0; i < 16; i++) {
                int c2 = chalf * 32 + 2 * i;
                float x0 = ip[(size_t)(2 * i) * HW * HW];
                float x1 = ip[(size_t)(2 * i + 1) * HW * HW];
                float v0 = fmaf(fmaf(P21, x0, P11), x0, P01);
                float v1 = fmaf(fmaf(P21, x1, P11), x1, P01);
                __nv_bfloat16 h0 = __float2bfloat16(v0), h1 = __float2bfloat16(v1);
                __nv_bfloat16 l0 = __float2bfloat16(v0 - __bfloat162float(h0));
                __nv_bfloat16 l1 = __float2bfloat16(v1 - __bfloat162float(h1));
                uint32_t hp = ((uint32_t)__bfloat16_as_ushort(h1) << 16) | __bfloat16_as_ushort(h0);
                uint32_t lp = ((uint32_t)__bfloat16_as_ushort(l1) << 16) | __bfloat16_as_ushort(l0);
                int off = rs * 128 + ((((c2 >> 3) ^ (rs & 7))) << 4) + (c2 & 7) * 2;
                *reinterpret_cast<uint32_t*>(a0 + off)         = hp;
                *reinterpret_cast<uint32_t*>(a0 + ATILE + off) = lp;
            }
        } else {
            for (int i = tid; i < 2 * ATILE / 4; i += 256)
                reinterpret_cast<uint32_t*>(a0)[i] = 0u;
        }
    };
    // copy tap-row group g (taps g*3..g*3+2, both parts) into B buffer
    auto fillB = [&](int g, int bbuf) {
        const uint32_t* gw = reinterpret_cast<const uint32_t*>(g_wsplit);
        char* bb = dsm + BOFF + bbuf * BGRP;
        for (int j = tid; j < 6 * 2048; j += 256) {
            int tile = j >> 11, rem = j & 2047;
            int s = tile >> 1, part = tile & 1;
            int nr = rem >> 5, kp = rem & 31;
            uint32_t v = gw[((g * 3 + s) * 2 + part) * 2048 + rem];
            *reinterpret_cast<uint32_t*>(bb + tile * BTILE + nr * 128 +
                (((kp >> 2) ^ (nr & 7)) << 4) + (kp & 3) * 4) = v;
        }
    };

    // prologue: halo rows of all slots, first two A rows, B group 0
    for (int j = tid; j < 3 * 2 * 2 * 32; j += 256) {
        int slot = j >> 7, rem = j & 127;
        int part = rem >> 6, rw = (rem >> 5) & 1, col = rem & 31;
        *reinterpret_cast<uint32_t*>(dsm + AOFF + (slot * 2 + part) * ATILE +
                                     (rw ? 129 : 0) * 128 + col * 4) = 0u;
    }
    fillA(yb - 1, 0);
    fillA(yb,     1);
    fillB(0, 0);
    __syncthreads();

    float acc[2][8][4];
    #pragma unroll
    for (int yi = 0; yi < 2; yi++)
        #pragma unroll
        for (int nt = 0; nt < 8; nt++)
            #pragma unroll
            for (int e = 0; e < 4; e++) acc[yi][nt][e] = 0.f;

    for (int r = 0; r < 3; r++) {
        const uint32_t abase0 = sb + AOFF + (r % 3) * 2 * ATILE;        // z = yb-1+r
        const uint32_t abase1 = sb + AOFF + ((r + 1) % 3) * 2 * ATILE;  // z = yb+r
        const uint32_t bbase  = sb + BOFF + (r & 1) * BGRP;

        #pragma unroll
        for (int s = 0; s < 3; s++) {
            uint32_t af[2][2][4][4];
            const int rowA = p0 + s + (lane & 7) + ((lane >> 3) & 1) * 8;
            const int chA  = lane >> 4;
            #pragma unroll
            for (int yi = 0; yi < 2; yi++) {
                uint32_t ay = (yi ? abase1 : abase0) + rowA * 128;
                #pragma unroll
                for (int part = 0; part < 2; part++) {
                    #pragma unroll
                    for (int kc = 0; kc < 4; kc++) {
                        int ch = 2 * kc + chA;
                        ldsm4(af[yi][part][kc], ay + part * ATILE + ((ch ^ (rowA & 7)) << 4));
                    }
                }
            }
            const uint32_t btile = bbase + s * 2 * BTILE;
            #pragma unroll
            for (int nt2 = 0; nt2 < 4; nt2++) {
                uint32_t bf[2][4][4];
                const int nrow = (nt2 * 2 + (lane >> 4)) * 8 + (lane & 7);
                #pragma unroll
                for (int part = 0; part < 2; part++)
                    #pragma unroll
                    for (int kc = 0; kc < 4; kc++) {
                        int ch = 2 * kc + ((lane >> 3) & 1);
                        ldsm4(bf[part][kc],
                              btile + part * BTILE + nrow * 128 + ((ch ^ (nrow & 7)) << 4));
                    }
                #pragma unroll
                for (int kc = 0; kc < 4; kc++)
                    #pragma unroll
                    for (int yi = 0; yi < 2; yi++) {
                        mma_bf16(acc[yi][nt2 * 2],     af[yi][0][kc], bf[0][kc]);      // hh
                        mma_bf16(acc[yi][nt2 * 2 + 1], af[yi][0][kc], bf[0][kc] + 2);
                        mma_bf16(acc[yi][nt2 * 2],     af[yi][1][kc], bf[0][kc]);      // lh
                        mma_bf16(acc[yi][nt2 * 2 + 1], af[yi][1][kc], bf[0][kc] + 2);
                        mma_bf16(acc[yi][nt2 * 2],     af[yi][0][kc], bf[1][kc]);      // hl
                        mma_bf16(acc[yi][nt2 * 2 + 1], af[yi][0][kc], bf[1][kc] + 2);
                    }
            }
        }

        if (r < 2) {
            fillA(yb + r + 1, (r + 2) % 3);   // writes slot unused by compute r
            fillB(r + 1, (r + 1) & 1);        // writes other B buffer
        }
        __syncthreads();
    }

    // epilogue: scale by 1/27
    const float sc = 1.f / 27.f;
    #pragma unroll
    for (int yi = 0; yi < 2; yi++) {
        const int y = yb + yi;
        #pragma unroll
        for (int nt = 0; nt < 8; nt++) {
            int kout = nt * 8 + 2 * (lane & 3);
            int pxo  = p0 + (lane >> 2);
            float* o = out + ((size_t)(n * COUT + kout) * HW + y) * HW;
            o[pxo]               = acc[yi][nt][0] * sc;
            o[HW * HW + pxo]     = acc[yi][nt][1] * sc;
            o[pxo + 8]           = acc[yi][nt][2] * sc;
            o[HW * HW + pxo + 8] = acc[yi][nt][3] * sc;
        }
    }
}

extern "C" void kernel_launch(void* const* d_in, const int* in_sizes, int n_in,
                              void* d_out, int out_size)
{
    const float* img = (const float*)d_in[0];
    const float* wgt = (const float*)d_in[1];
    float* out = (float*)d_out;

    cudaFuncSetAttribute(conv_hmma_kernel,
                         cudaFuncAttributeMaxDynamicSharedMemorySize, DSMEM);

    int N = in_sizes[0] / (CIN * HW * HW);   // 16
    wprep_kernel<<<144, 256>>>(wgt);
    conv_hmma_kernel<<<N * 64, 256, DSMEM>>>(img, out);
}